// round 15
// baseline (speedup 1.0000x reference)
#include <cuda_runtime.h>

// ---------------------------------------------------------------------------
// 3-layer stacked LSTM (batch=1), T=4096, IN=64, H=1024, OUT=1, fp32.
//
// Recurrence sync: two-hop aggregator barrier, NO atomics, NO strong bulk ops.
//   arrive  : each CTA tid0: membar.gpu + relaxed st of epoch to own flag line
//   aggregate: CTA0 warp 8 (dedicated) polls all 128 flags (acquire, 4/lane),
//              ballots, lane0 release-stores the master epoch
//   observe : warp-8 lane0 of every other CTA acquire-polls master only
// Bulk h exchange stays weak ld.global.cg (L1-bypass) — strong loads for bulk
// data were the R13/R14 regression.
// ---------------------------------------------------------------------------

#define T_STEPS 4096
#define HID     1024
#define GATES   4096
#define NCTA    128

typedef unsigned long long ull;

// Static scratch (allocation-free).
__device__ float    g_pre[(size_t)T_STEPS * GATES];   // 64 MB
__device__ float    g_hsA[(size_t)T_STEPS * HID];     // 16 MB (layers 0, 2)
__device__ float    g_hsB[(size_t)T_STEPS * HID];     // 16 MB (layer 1)
__device__ unsigned g_flags[NCTA * 32];               // per-CTA flag, 128B apart
__device__ unsigned g_master[32];                     // aggregated epoch

// ---- sm_103a packed-fp32 / memory helpers ---------------------------------

__device__ __forceinline__ void fma2(ull& d, ull a, ull b) {
    asm("fma.rn.f32x2 %0, %1, %2, %0;" : "+l"(d) : "l"(a), "l"(b));
}
__device__ __forceinline__ ull pack2(float x, float y) {
    ull r; asm("mov.b64 %0, {%1, %2};" : "=l"(r) : "f"(x), "f"(y)); return r;
}
__device__ __forceinline__ float2 unpack2(ull v) {
    float2 f; asm("mov.b64 {%0, %1}, %2;" : "=f"(f.x), "=f"(f.y) : "l"(v)); return f;
}
// Weak L1-bypassing 8B load for cross-SM h data.
__device__ __forceinline__ ull ldcg_u64(const float* p) {
    ull v; asm volatile("ld.global.cg.b64 %0, [%1];" : "=l"(v) : "l"(p)); return v;
}
// Strong 4B ops for the tiny flag protocol only.
__device__ __forceinline__ unsigned ld_acq32(const unsigned* p) {
    unsigned v; asm volatile("ld.acquire.gpu.global.u32 %0, [%1];" : "=r"(v) : "l"(p)); return v;
}
__device__ __forceinline__ void st_rel32(unsigned* p, unsigned v) {
    asm volatile("st.release.gpu.global.u32 [%0], %1;" :: "l"(p), "r"(v) : "memory");
}
__device__ __forceinline__ void st_rlx32(unsigned* p, unsigned v) {
    asm volatile("st.relaxed.gpu.global.u32 [%0], %1;" :: "l"(p), "r"(v) : "memory");
}
__device__ __forceinline__ float fast_tanh(float x) {
    return 1.f - __fdividef(2.f, __expf(2.f * x) + 1.f);
}

// ---- GEMM: g_pre[t, r] = sum_k A[t,k]*W[r,k] + b1[r] + b2[r] ---------------
// gemm0 (src_sel==0) also resets the barrier flags + master (block (0,0));
// stream order guarantees this completes before rec0 starts, every replay.

#define GT  64
#define GR  64
#define GKC 16

__global__ void __launch_bounds__(256) k_gemm(
    const float* __restrict__ Ain, int src_sel, int K,
    const float* __restrict__ W,
    const float* __restrict__ b1, const float* __restrict__ b2)
{
    if (src_sel == 0 && blockIdx.x == 0 && blockIdx.y == 0) {
        if (threadIdx.x < NCTA) g_flags[threadIdx.x * 32] = 0u;
        if (threadIdx.x == NCTA) g_master[0] = 0u;
    }

    const float* A = (src_sel == 1) ? g_hsA : (src_sel == 2) ? g_hsB : Ain;
    float* C = g_pre;

    __shared__ float As[GKC][GT + 4];
    __shared__ float Ws[GKC][GR + 4];

    const int t0   = blockIdx.y * GT;
    const int r0   = blockIdx.x * GR;
    const int tx   = threadIdx.x & 15;
    const int ty   = threadIdx.x >> 4;
    const int lrow = threadIdx.x >> 2;
    const int lcol = (threadIdx.x & 3) * 4;

    ull acc[4][2];
#pragma unroll
    for (int i = 0; i < 4; ++i) { acc[i][0] = 0ull; acc[i][1] = 0ull; }

    for (int kk = 0; kk < K; kk += GKC) {
        float4 va = *(const float4*)(A + (size_t)(t0 + lrow) * K + kk + lcol);
        float4 vw = *(const float4*)(W + (size_t)(r0 + lrow) * K + kk + lcol);
        As[lcol + 0][lrow] = va.x; As[lcol + 1][lrow] = va.y;
        As[lcol + 2][lrow] = va.z; As[lcol + 3][lrow] = va.w;
        Ws[lcol + 0][lrow] = vw.x; Ws[lcol + 1][lrow] = vw.y;
        Ws[lcol + 2][lrow] = vw.z; Ws[lcol + 3][lrow] = vw.w;
        __syncthreads();
#pragma unroll
        for (int k = 0; k < GKC; ++k) {
            float4 a = *(const float4*)&As[k][4 * ty];
            const ull* wp = (const ull*)&Ws[k][4 * tx];
            ull w0 = wp[0], w1 = wp[1];
            ull ap;
            ap = pack2(a.x, a.x); fma2(acc[0][0], ap, w0); fma2(acc[0][1], ap, w1);
            ap = pack2(a.y, a.y); fma2(acc[1][0], ap, w0); fma2(acc[1][1], ap, w1);
            ap = pack2(a.z, a.z); fma2(acc[2][0], ap, w0); fma2(acc[2][1], ap, w1);
            ap = pack2(a.w, a.w); fma2(acc[3][0], ap, w0); fma2(acc[3][1], ap, w1);
        }
        __syncthreads();
    }

    const int r = r0 + 4 * tx;
    float4 bias;
    bias.x = b1[r + 0] + b2[r + 0];
    bias.y = b1[r + 1] + b2[r + 1];
    bias.z = b1[r + 2] + b2[r + 2];
    bias.w = b1[r + 3] + b2[r + 3];
#pragma unroll
    for (int i = 0; i < 4; ++i) {
        float2 p0 = unpack2(acc[i][0]);
        float2 p1 = unpack2(acc[i][1]);
        float4 o;
        o.x = p0.x + bias.x; o.y = p0.y + bias.y;
        o.z = p1.x + bias.z; o.w = p1.y + bias.w;
        *(float4*)(C + (size_t)(t0 + 4 * ty + i) * GATES + r) = o;
    }
}

// ---- Persistent recurrent kernel -------------------------------------------
// 128 CTAs x 288 threads (9 warps; all resident). Work warps 0-7: warp w owns
// unit b*8+w, lane l keeps W_hh cols {64k+2l, 64k+2l+1} (k=0..15) in regs.
// Warp 8: barrier warp (CTA0: aggregator; others: master waiter).
// Per step t:
//   warp8: wait (aggregate flags -> master, or poll master) for epoch base+t
//   SYNC  -> work warps: 16x ldcg.64 h(t-1) -> 64 fma2 -> xor-reduce ->
//            lane0 gates -> STG h(t)
//   SYNC  -> tid0: membar.gpu; flag = base+t+1

__global__ void __launch_bounds__(288, 1) k_rec(
    const float* __restrict__ whh, int out_sel, int layer)
{
    float* hs = (out_sel == 0) ? g_hsA : g_hsB;
    const float* pre = g_pre;

    const int tid  = threadIdx.x;
    const int w    = tid >> 5;
    const int l    = tid & 31;
    const int unit = blockIdx.x * 8 + (w & 7);
    const unsigned ebase = (unsigned)(layer * T_STEPS);

    // Register-resident W_hh slice (work warps only).
    ull wgt[4][16];
    if (w < 8) {
#pragma unroll
        for (int g = 0; g < 4; ++g) {
            const float* row = whh + (size_t)(g * HID + unit) * HID + 2 * l;
#pragma unroll
            for (int k = 0; k < 16; ++k)
                wgt[g][k] = *(const ull*)(row + 64 * k);
        }
    }

    float c_state = 0.f;
    float p0 = 0.f, p1 = 0.f, p2 = 0.f, p3 = 0.f;
    if (w < 8 && l == 0) {
        p0 = pre[0 * HID + unit];
        p1 = pre[1 * HID + unit];
        p2 = pre[2 * HID + unit];
        p3 = pre[3 * HID + unit];
    }

    // Aggregator lane's 4 assigned flag lines.
    const unsigned* fp0 = &g_flags[(4 * l + 0) * 32];
    const unsigned* fp1 = &g_flags[(4 * l + 1) * 32];
    const unsigned* fp2 = &g_flags[(4 * l + 2) * 32];
    const unsigned* fp3 = &g_flags[(4 * l + 3) * 32];

    for (int t = 0; t < T_STEPS; ++t) {
        // ---- barrier warp: wait for global step t-1 completion ----
        if (t > 0 && w == 8) {
            const unsigned target = ebase + (unsigned)t;
            if (blockIdx.x == 0) {
                bool ok;
                do {
                    ok = (ld_acq32(fp0) >= target) & (ld_acq32(fp1) >= target)
                       & (ld_acq32(fp2) >= target) & (ld_acq32(fp3) >= target);
                } while (__ballot_sync(0xffffffffu, ok) != 0xffffffffu);
                if (l == 0) st_rel32(g_master, target);
            } else if (l == 0) {
                while (ld_acq32(g_master) < target) { }
            }
        }
        __syncthreads();

        // ---- work warps: recurrent matvec + gates ----
        if (w < 8) {
            // Prefetch next step's pre (off the critical chain).
            float n0 = 0.f, n1 = 0.f, n2 = 0.f, n3 = 0.f;
            if (l == 0 && t + 1 < T_STEPS) {
                const float* pr = pre + (size_t)(t + 1) * GATES + unit;
                n0 = pr[0 * HID]; n1 = pr[1 * HID];
                n2 = pr[2 * HID]; n3 = pr[3 * HID];
            }

            float d0 = 0.f, d1 = 0.f, d2 = 0.f, d3 = 0.f;
            if (t > 0) {
                const float* hrow = hs + (size_t)(t - 1) * HID + 2 * l;
                ull a0 = 0ull, a1 = 0ull, a2 = 0ull, a3 = 0ull;
#pragma unroll
                for (int k = 0; k < 16; ++k) {
                    ull hv = ldcg_u64(hrow + 64 * k);
                    fma2(a0, wgt[0][k], hv);
                    fma2(a1, wgt[1][k], hv);
                    fma2(a2, wgt[2][k], hv);
                    fma2(a3, wgt[3][k], hv);
                }
                float2 f0 = unpack2(a0), f1 = unpack2(a1);
                float2 f2 = unpack2(a2), f3 = unpack2(a3);
                d0 = f0.x + f0.y; d1 = f1.x + f1.y;
                d2 = f2.x + f2.y; d3 = f3.x + f3.y;
#pragma unroll
                for (int s = 16; s > 0; s >>= 1) {
                    d0 += __shfl_xor_sync(0xffffffffu, d0, s);
                    d1 += __shfl_xor_sync(0xffffffffu, d1, s);
                    d2 += __shfl_xor_sync(0xffffffffu, d2, s);
                    d3 += __shfl_xor_sync(0xffffffffu, d3, s);
                }
            }

            if (l == 0) {
                float gi = 1.f / (1.f + __expf(-(p0 + d0)));
                float gf = 1.f / (1.f + __expf(-(p1 + d1)));
                float gg = fast_tanh(p2 + d2);
                float go = 1.f / (1.f + __expf(-(p3 + d3)));
                c_state = gf * c_state + gi * gg;
                float h = go * fast_tanh(c_state);
                hs[(size_t)t * HID + unit] = h;
                p0 = n0; p1 = n1; p2 = n2; p3 = n3;
            }
        }
        __syncthreads();

        // ---- arrive: one relaxed store to this CTA's own flag line ----
        if (tid == 0) {
            __threadfence();                       // publish this CTA's h(t)
            st_rlx32(&g_flags[blockIdx.x * 32], ebase + (unsigned)t + 1u);
        }
    }
}

// ---- Final linear layer ----------------------------------------------------

__global__ void k_final(const float* __restrict__ wlin,
                        const float* __restrict__ blin,
                        float* __restrict__ out)
{
    const float* h = g_hsA + (size_t)(T_STEPS - 1) * HID;
    __shared__ float red[8];
    float s = 0.f;
    for (int j = threadIdx.x; j < HID; j += 256)
        s += h[j] * wlin[j];
#pragma unroll
    for (int sh = 16; sh > 0; sh >>= 1)
        s += __shfl_xor_sync(0xffffffffu, s, sh);
    if ((threadIdx.x & 31) == 0) red[threadIdx.x >> 5] = s;
    __syncthreads();
    if (threadIdx.x < 8) {
        s = red[threadIdx.x];
#pragma unroll
        for (int sh = 4; sh > 0; sh >>= 1)
            s += __shfl_xor_sync(0x000000ffu, s, sh);
        if (threadIdx.x == 0) out[0] = s + blin[0];
    }
}

// ---- launch ----------------------------------------------------------------
// Launch indices: 0=gemm0 1=rec0 2=gemm1 3=rec1 4=gemm2 5=rec2(<- ncu) 6=final

extern "C" void kernel_launch(void* const* d_in, const int* in_sizes, int n_in,
                              void* d_out, int out_size)
{
    const float* seq   = (const float*)d_in[0];
    const float* w_ih0 = (const float*)d_in[1];
    const float* w_hh0 = (const float*)d_in[2];
    const float* b_ih0 = (const float*)d_in[3];
    const float* b_hh0 = (const float*)d_in[4];
    const float* w_ih1 = (const float*)d_in[5];
    const float* w_hh1 = (const float*)d_in[6];
    const float* b_ih1 = (const float*)d_in[7];
    const float* b_hh1 = (const float*)d_in[8];
    const float* w_ih2 = (const float*)d_in[9];
    const float* w_hh2 = (const float*)d_in[10];
    const float* b_ih2 = (const float*)d_in[11];
    const float* b_hh2 = (const float*)d_in[12];
    const float* w_lin = (const float*)d_in[13];
    const float* b_lin = (const float*)d_in[14];
    float* out = (float*)d_out;

    const dim3 ggrid(GATES / GR, T_STEPS / GT);

    // Layer 0: input dim 64 (also resets barrier state for this replay)
    k_gemm<<<ggrid, 256>>>(seq, 0, 64, w_ih0, b_ih0, b_hh0);
    k_rec<<<NCTA, 288>>>(w_hh0, /*out=*/0, /*layer=*/0);
    // Layer 1: reads g_hsA
    k_gemm<<<ggrid, 256>>>(nullptr, 1, HID, w_ih1, b_ih1, b_hh1);
    k_rec<<<NCTA, 288>>>(w_hh1, /*out=*/1, /*layer=*/1);
    // Layer 2: reads g_hsB
    k_gemm<<<ggrid, 256>>>(nullptr, 2, HID, w_ih2, b_ih2, b_hh2);
    k_rec<<<NCTA, 288>>>(w_hh2, /*out=*/0, /*layer=*/2);
    // Output
    k_final<<<1, 256>>>(w_lin, b_lin, out);
}

// round 17
// speedup vs baseline: 1.2939x; 1.2939x over previous
#include <cuda_runtime.h>

// ---------------------------------------------------------------------------
// 3-layer stacked LSTM (batch=1), T=4096, IN=64, H=1024, OUT=1, fp32.
//
// Recurrence sync: single-hop per-CTA flag barrier, no atomics.
//   arrive : __syncthreads; tid0: __threadfence + st.relaxed epoch -> own
//            128B-spaced flag line (128 independent stores, zero L2-ALU
//            serialization)
//   wait   : dedicated warp 8 per CTA polls all 128 flags with STRONG
//            ld.relaxed (4 independent flags/lane -> MLP-4; strong loads
//            guarantee eventual visibility — weak .cg polls hang, R16),
//            __ballot until all pass, one fence.acq_rel.gpu, __syncthreads.
// Bulk h exchange: weak ld.global.cg (L1-bypass) only.
// ---------------------------------------------------------------------------

#define T_STEPS 4096
#define HID     1024
#define GATES   4096
#define NCTA    128

typedef unsigned long long ull;

// Static scratch (allocation-free).
__device__ float    g_pre[(size_t)T_STEPS * GATES];   // 64 MB
__device__ float    g_hsA[(size_t)T_STEPS * HID];     // 16 MB (layers 0, 2)
__device__ float    g_hsB[(size_t)T_STEPS * HID];     // 16 MB (layer 1)
__device__ unsigned g_flags[NCTA * 32];               // per-CTA flag, 128B apart

// ---- sm_103a packed-fp32 / memory helpers ---------------------------------

__device__ __forceinline__ void fma2(ull& d, ull a, ull b) {
    asm("fma.rn.f32x2 %0, %1, %2, %0;" : "+l"(d) : "l"(a), "l"(b));
}
__device__ __forceinline__ ull pack2(float x, float y) {
    ull r; asm("mov.b64 %0, {%1, %2};" : "=l"(r) : "f"(x), "f"(y)); return r;
}
__device__ __forceinline__ float2 unpack2(ull v) {
    float2 f; asm("mov.b64 {%0, %1}, %2;" : "=f"(f.x), "=f"(f.y) : "l"(v)); return f;
}
// Weak L1-bypassing 8B load for cross-SM bulk h data.
__device__ __forceinline__ ull ldcg_u64(const float* p) {
    ull v; asm volatile("ld.global.cg.b64 %0, [%1];" : "=l"(v) : "l"(p)); return v;
}
// STRONG relaxed 4B load for flag polls (coherent; eventual visibility).
__device__ __forceinline__ unsigned ld_rlx32(const unsigned* p) {
    unsigned v; asm volatile("ld.relaxed.gpu.global.u32 %0, [%1];" : "=r"(v) : "l"(p)); return v;
}
__device__ __forceinline__ void st_rlx32(unsigned* p, unsigned v) {
    asm volatile("st.relaxed.gpu.global.u32 [%0], %1;" :: "l"(p), "r"(v) : "memory");
}
__device__ __forceinline__ void fence_acq() {
    asm volatile("fence.acq_rel.gpu;" ::: "memory");
}
__device__ __forceinline__ float fast_tanh(float x) {
    return 1.f - __fdividef(2.f, __expf(2.f * x) + 1.f);
}

// ---- GEMM: g_pre[t, r] = sum_k A[t,k]*W[r,k] + b1[r] + b2[r] ---------------
// gemm0 (src_sel==0) also resets the barrier flags (block (0,0)); kernel
// boundaries serialize this before rec0, every graph replay.

#define GT  64
#define GR  64
#define GKC 16

__global__ void __launch_bounds__(256) k_gemm(
    const float* __restrict__ Ain, int src_sel, int K,
    const float* __restrict__ W,
    const float* __restrict__ b1, const float* __restrict__ b2)
{
    if (src_sel == 0 && blockIdx.x == 0 && blockIdx.y == 0 && threadIdx.x < NCTA)
        g_flags[threadIdx.x * 32] = 0u;

    const float* A = (src_sel == 1) ? g_hsA : (src_sel == 2) ? g_hsB : Ain;
    float* C = g_pre;

    __shared__ float As[GKC][GT + 4];
    __shared__ float Ws[GKC][GR + 4];

    const int t0   = blockIdx.y * GT;
    const int r0   = blockIdx.x * GR;
    const int tx   = threadIdx.x & 15;
    const int ty   = threadIdx.x >> 4;
    const int lrow = threadIdx.x >> 2;
    const int lcol = (threadIdx.x & 3) * 4;

    ull acc[4][2];
#pragma unroll
    for (int i = 0; i < 4; ++i) { acc[i][0] = 0ull; acc[i][1] = 0ull; }

    for (int kk = 0; kk < K; kk += GKC) {
        float4 va = *(const float4*)(A + (size_t)(t0 + lrow) * K + kk + lcol);
        float4 vw = *(const float4*)(W + (size_t)(r0 + lrow) * K + kk + lcol);
        As[lcol + 0][lrow] = va.x; As[lcol + 1][lrow] = va.y;
        As[lcol + 2][lrow] = va.z; As[lcol + 3][lrow] = va.w;
        Ws[lcol + 0][lrow] = vw.x; Ws[lcol + 1][lrow] = vw.y;
        Ws[lcol + 2][lrow] = vw.z; Ws[lcol + 3][lrow] = vw.w;
        __syncthreads();
#pragma unroll
        for (int k = 0; k < GKC; ++k) {
            float4 a = *(const float4*)&As[k][4 * ty];
            const ull* wp = (const ull*)&Ws[k][4 * tx];
            ull w0 = wp[0], w1 = wp[1];
            ull ap;
            ap = pack2(a.x, a.x); fma2(acc[0][0], ap, w0); fma2(acc[0][1], ap, w1);
            ap = pack2(a.y, a.y); fma2(acc[1][0], ap, w0); fma2(acc[1][1], ap, w1);
            ap = pack2(a.z, a.z); fma2(acc[2][0], ap, w0); fma2(acc[2][1], ap, w1);
            ap = pack2(a.w, a.w); fma2(acc[3][0], ap, w0); fma2(acc[3][1], ap, w1);
        }
        __syncthreads();
    }

    const int r = r0 + 4 * tx;
    float4 bias;
    bias.x = b1[r + 0] + b2[r + 0];
    bias.y = b1[r + 1] + b2[r + 1];
    bias.z = b1[r + 2] + b2[r + 2];
    bias.w = b1[r + 3] + b2[r + 3];
#pragma unroll
    for (int i = 0; i < 4; ++i) {
        float2 p0 = unpack2(acc[i][0]);
        float2 p1 = unpack2(acc[i][1]);
        float4 o;
        o.x = p0.x + bias.x; o.y = p0.y + bias.y;
        o.z = p1.x + bias.z; o.w = p1.y + bias.w;
        *(float4*)(C + (size_t)(t0 + 4 * ty + i) * GATES + r) = o;
    }
}

// ---- Persistent recurrent kernel -------------------------------------------
// 128 CTAs x 288 threads (9 warps; all resident). Work warps 0-7: warp w owns
// unit b*8+w; lane l keeps W_hh cols {64k+2l, 64k+2l+1} (k=0..15) in regs.
// Warp 8: poll warp (strong relaxed loads of 4 flags/lane + ballot + fence).
// Per step t:
//   warp8 waits for all 128 flags >= ebase+t  ->  SYNC  ->
//   work warps: 16x ldcg.64 h(t-1) -> 64 fma2 -> xor-reduce -> lane0 gates
//   -> STG h(t)  ->  SYNC  ->  tid0: threadfence + relaxed flag = ebase+t+1

__global__ void __launch_bounds__(288, 1) k_rec(
    const float* __restrict__ whh, int out_sel, int layer)
{
    float* hs = (out_sel == 0) ? g_hsA : g_hsB;
    const float* pre = g_pre;

    const int tid  = threadIdx.x;
    const int w    = tid >> 5;
    const int l    = tid & 31;
    const int unit = blockIdx.x * 8 + (w & 7);
    const unsigned ebase = (unsigned)(layer * T_STEPS);

    // Register-resident W_hh slice (work warps only).
    ull wgt[4][16];
    if (w < 8) {
#pragma unroll
        for (int g = 0; g < 4; ++g) {
            const float* row = whh + (size_t)(g * HID + unit) * HID + 2 * l;
#pragma unroll
            for (int k = 0; k < 16; ++k)
                wgt[g][k] = *(const ull*)(row + 64 * k);
        }
    }

    float c_state = 0.f;
    float p0 = 0.f, p1 = 0.f, p2 = 0.f, p3 = 0.f;
    if (w < 8 && l == 0) {
        p0 = pre[0 * HID + unit];
        p1 = pre[1 * HID + unit];
        p2 = pre[2 * HID + unit];
        p3 = pre[3 * HID + unit];
    }

    // Poll warp: 4 independent flag lines per lane (MLP-4 strong loads).
    const unsigned* fp0 = &g_flags[(4 * l + 0) * 32];
    const unsigned* fp1 = &g_flags[(4 * l + 1) * 32];
    const unsigned* fp2 = &g_flags[(4 * l + 2) * 32];
    const unsigned* fp3 = &g_flags[(4 * l + 3) * 32];

    for (int t = 0; t < T_STEPS; ++t) {
        // ---- wait: all CTAs must have published step t-1 ----
        if (t > 0 && w == 8) {
            const unsigned target = ebase + (unsigned)t;
            bool ok;
            unsigned f0 = ld_rlx32(fp0);
            unsigned f1 = ld_rlx32(fp1);
            unsigned f2 = ld_rlx32(fp2);
            unsigned f3 = ld_rlx32(fp3);
            ok = (f0 >= target) & (f1 >= target) &
                 (f2 >= target) & (f3 >= target);
            while (__ballot_sync(0xffffffffu, ok) != 0xffffffffu) {
                __nanosleep(32);
                f0 = ld_rlx32(fp0);
                f1 = ld_rlx32(fp1);
                f2 = ld_rlx32(fp2);
                f3 = ld_rlx32(fp3);
                ok = (f0 >= target) & (f1 >= target) &
                     (f2 >= target) & (f3 >= target);
            }
            fence_acq();   // order subsequent h reads after observed flags
        }
        __syncthreads();

        // ---- work warps: recurrent matvec + gates ----
        if (w < 8) {
            // Prefetch next step's pre (off the critical chain).
            float n0 = 0.f, n1 = 0.f, n2 = 0.f, n3 = 0.f;
            if (l == 0 && t + 1 < T_STEPS) {
                const float* pr = pre + (size_t)(t + 1) * GATES + unit;
                n0 = pr[0 * HID]; n1 = pr[1 * HID];
                n2 = pr[2 * HID]; n3 = pr[3 * HID];
            }

            float d0 = 0.f, d1 = 0.f, d2 = 0.f, d3 = 0.f;
            if (t > 0) {
                const float* hrow = hs + (size_t)(t - 1) * HID + 2 * l;
                ull a0 = 0ull, a1 = 0ull, a2 = 0ull, a3 = 0ull;
#pragma unroll
                for (int k = 0; k < 16; ++k) {
                    ull hv = ldcg_u64(hrow + 64 * k);
                    fma2(a0, wgt[0][k], hv);
                    fma2(a1, wgt[1][k], hv);
                    fma2(a2, wgt[2][k], hv);
                    fma2(a3, wgt[3][k], hv);
                }
                float2 f0 = unpack2(a0), f1 = unpack2(a1);
                float2 f2 = unpack2(a2), f3 = unpack2(a3);
                d0 = f0.x + f0.y; d1 = f1.x + f1.y;
                d2 = f2.x + f2.y; d3 = f3.x + f3.y;
#pragma unroll
                for (int s = 16; s > 0; s >>= 1) {
                    d0 += __shfl_xor_sync(0xffffffffu, d0, s);
                    d1 += __shfl_xor_sync(0xffffffffu, d1, s);
                    d2 += __shfl_xor_sync(0xffffffffu, d2, s);
                    d3 += __shfl_xor_sync(0xffffffffu, d3, s);
                }
            }

            if (l == 0) {
                float gi = 1.f / (1.f + __expf(-(p0 + d0)));
                float gf = 1.f / (1.f + __expf(-(p1 + d1)));
                float gg = fast_tanh(p2 + d2);
                float go = 1.f / (1.f + __expf(-(p3 + d3)));
                c_state = gf * c_state + gi * gg;
                float h = go * fast_tanh(c_state);
                hs[(size_t)t * HID + unit] = h;
                p0 = n0; p1 = n1; p2 = n2; p3 = n3;
            }
        }
        __syncthreads();

        // ---- arrive: drain SM stores, then one relaxed flag store ----
        if (tid == 0) {
            __threadfence();
            st_rlx32(&g_flags[blockIdx.x * 32], ebase + (unsigned)t + 1u);
        }
    }
}

// ---- Final linear layer ----------------------------------------------------

__global__ void k_final(const float* __restrict__ wlin,
                        const float* __restrict__ blin,
                        float* __restrict__ out)
{
    const float* h = g_hsA + (size_t)(T_STEPS - 1) * HID;
    __shared__ float red[8];
    float s = 0.f;
    for (int j = threadIdx.x; j < HID; j += 256)
        s += h[j] * wlin[j];
#pragma unroll
    for (int sh = 16; sh > 0; sh >>= 1)
        s += __shfl_xor_sync(0xffffffffu, s, sh);
    if ((threadIdx.x & 31) == 0) red[threadIdx.x >> 5] = s;
    __syncthreads();
    if (threadIdx.x < 8) {
        s = red[threadIdx.x];
#pragma unroll
        for (int sh = 4; sh > 0; sh >>= 1)
            s += __shfl_xor_sync(0x000000ffu, s, sh);
        if (threadIdx.x == 0) out[0] = s + blin[0];
    }
}

// ---- launch ----------------------------------------------------------------
// Launch indices: 0=gemm0 1=rec0 2=gemm1 3=rec1 4=gemm2 5=rec2(<- ncu) 6=final

extern "C" void kernel_launch(void* const* d_in, const int* in_sizes, int n_in,
                              void* d_out, int out_size)
{
    const float* seq   = (const float*)d_in[0];
    const float* w_ih0 = (const float*)d_in[1];
    const float* w_hh0 = (const float*)d_in[2];
    const float* b_ih0 = (const float*)d_in[3];
    const float* b_hh0 = (const float*)d_in[4];
    const float* w_ih1 = (const float*)d_in[5];
    const float* w_hh1 = (const float*)d_in[6];
    const float* b_ih1 = (const float*)d_in[7];
    const float* b_hh1 = (const float*)d_in[8];
    const float* w_ih2 = (const float*)d_in[9];
    const float* w_hh2 = (const float*)d_in[10];
    const float* b_ih2 = (const float*)d_in[11];
    const float* b_hh2 = (const float*)d_in[12];
    const float* w_lin = (const float*)d_in[13];
    const float* b_lin = (const float*)d_in[14];
    float* out = (float*)d_out;

    const dim3 ggrid(GATES / GR, T_STEPS / GT);

    // Layer 0: input dim 64 (also resets barrier flags for this replay)
    k_gemm<<<ggrid, 256>>>(seq, 0, 64, w_ih0, b_ih0, b_hh0);
    k_rec<<<NCTA, 288>>>(w_hh0, /*out=*/0, /*layer=*/0);
    // Layer 1: reads g_hsA
    k_gemm<<<ggrid, 256>>>(nullptr, 1, HID, w_ih1, b_ih1, b_hh1);
    k_rec<<<NCTA, 288>>>(w_hh1, /*out=*/1, /*layer=*/1);
    // Layer 2: reads g_hsB
    k_gemm<<<ggrid, 256>>>(nullptr, 2, HID, w_ih2, b_ih2, b_hh2);
    k_rec<<<NCTA, 288>>>(w_hh2, /*out=*/0, /*layer=*/2);
    // Output
    k_final<<<1, 256>>>(w_lin, b_lin, out);
}